// round 2
// baseline (speedup 1.0000x reference)
#include <cuda_runtime.h>
#include <math.h>

#define B 16384
#define D 2048
#define E 16
#define C 64

// Scratch (no allocations allowed): routing buckets + counts.
__device__ int g_counts[E];
__device__ int g_bucket[E * B];

__global__ void zero_counts_kernel() {
    if (threadIdx.x < E) g_counts[threadIdx.x] = 0;
}

// ---- packed f32x2 helpers (SASS FFMA2 path, sm_103a) ----------------------
__device__ __forceinline__ unsigned long long pack2_dup(float x) {
    unsigned long long r;
    unsigned int u = __float_as_uint(x);
    asm("mov.b64 %0, {%1, %1};" : "=l"(r) : "r"(u));
    return r;
}
__device__ __forceinline__ unsigned long long ffma2(
    unsigned long long a, unsigned long long b, unsigned long long c) {
    unsigned long long d;
    asm("fma.rn.f32x2 %0, %1, %2, %3;" : "=l"(d) : "l"(a), "l"(b), "l"(c));
    return d;
}
__device__ __forceinline__ float2 unpack2(unsigned long long v) {
    unsigned int lo, hi;
    asm("mov.b64 {%0, %1}, %2;" : "=r"(lo), "=r"(hi) : "l"(v));
    return make_float2(__uint_as_float(lo), __uint_as_float(hi));
}

// ---------------------------------------------------------------------------
// Kernel 1: coarse router GEMM [B,16] + bias + argmax + bucket scatter.
// Block tile: 128 samples x 16 experts, 256 threads.
// Thread tile: 8 samples (4 packed pairs) x 1 expert, FFMA2.
// ---------------------------------------------------------------------------
#define C1_TM 128
#define C1_TK 32
#define C1_FS 132   // k-transposed feature tile row stride
#define C1_WS 20
#define C1_CS 20

__global__ __launch_bounds__(256) void coarse_kernel(
    const float* __restrict__ features,
    const float* __restrict__ cw,
    const float* __restrict__ cb,
    float* __restrict__ out_coarse,
    float* __restrict__ out_eid)
{
    __shared__ __align__(16) float fs[C1_TK][C1_FS];  // [k][sample]
    __shared__ __align__(16) float ws[C1_TK][C1_WS];  // [k][expert]
    __shared__ __align__(16) float cs[C1_TM][C1_CS];  // logits for epilogue

    int tid = threadIdx.x;
    int s0  = blockIdx.x * C1_TM;
    int oct = tid >> 4;   // sample octet 0..15
    int e   = tid & 15;   // expert

    unsigned long long acc[4] = {0ull, 0ull, 0ull, 0ull};

    for (int k0 = 0; k0 < D; k0 += C1_TK) {
        // stage features: 128 samples x 32 k = 1024 float4, 4 per thread
        #pragma unroll
        for (int it = 0; it < 4; it++) {
            int task = tid + it * 256;
            int s  = task >> 3;
            int kc = task & 7;
            float4 v = *(const float4*)(features + (size_t)(s0 + s) * D + k0 + kc * 4);
            fs[kc * 4 + 0][s] = v.x;
            fs[kc * 4 + 1][s] = v.y;
            fs[kc * 4 + 2][s] = v.z;
            fs[kc * 4 + 3][s] = v.w;
        }
        // stage coarse weights: 16 experts x 32 k = 128 float4
        if (tid < 128) {
            int we = tid >> 3;
            int kc = tid & 7;
            float4 w = *(const float4*)(cw + (size_t)we * D + k0 + kc * 4);
            ws[kc * 4 + 0][we] = w.x;
            ws[kc * 4 + 1][we] = w.y;
            ws[kc * 4 + 2][we] = w.z;
            ws[kc * 4 + 3][we] = w.w;
        }
        __syncthreads();

        #pragma unroll
        for (int kk = 0; kk < C1_TK; kk++) {
            ulonglong2 fa0 = *(const ulonglong2*)&fs[kk][oct * 8];
            ulonglong2 fa1 = *(const ulonglong2*)&fs[kk][oct * 8 + 4];
            unsigned long long w2 = pack2_dup(ws[kk][e]);
            acc[0] = ffma2(fa0.x, w2, acc[0]);
            acc[1] = ffma2(fa0.y, w2, acc[1]);
            acc[2] = ffma2(fa1.x, w2, acc[2]);
            acc[3] = ffma2(fa1.y, w2, acc[3]);
        }
        __syncthreads();
    }

    float bias = cb[e];
    #pragma unroll
    for (int p = 0; p < 4; p++) {
        float2 v = unpack2(acc[p]);
        cs[oct * 8 + 2 * p + 0][e] = v.x + bias;
        cs[oct * 8 + 2 * p + 1][e] = v.y + bias;
    }
    __syncthreads();

    if (tid < C1_TM) {
        int gs = s0 + tid;
        // store coarse logits (vectorized)
        #pragma unroll
        for (int j = 0; j < 4; j++) {
            float4 v = *(const float4*)&cs[tid][j * 4];
            *(float4*)(out_coarse + (size_t)gs * E + j * 4) = v;
        }
        // first-occurrence argmax (matches jnp.argmax)
        float m = cs[tid][0];
        int am = 0;
        #pragma unroll
        for (int j = 1; j < E; j++) {
            float v = cs[tid][j];
            if (v > m) { m = v; am = j; }
        }
        out_eid[gs] = (float)am;
        int pos = atomicAdd(&g_counts[am], 1);
        g_bucket[am * B + pos] = gs;
    }
}

// ---------------------------------------------------------------------------
// Kernel 2: per-expert gathered GEMM [cnt_e, 64] + bias + softmax + argmax.
// Block tile: 128 samples x 64 classes, 256 threads.
// Thread tile: 8 samples (4 packed pairs) x 4 classes, FFMA2.
// Logits tile (ys) aliases the staging tiles via a union buffer.
// ---------------------------------------------------------------------------
#define K2_TM 128
#define K2_TK 32
#define K2_FS 132
#define K2_WS 68
#define K2_YS 68

#define SZ_FS (K2_TK * K2_FS * 4)          // 16896
#define SZ_WS (K2_TK * K2_WS * 4)          // 8704
#define SZ_YS (K2_TM * K2_YS * 4)          // 34816

__global__ __launch_bounds__(256) void expert_kernel(
    const float* __restrict__ features,
    const float* __restrict__ ew,
    const float* __restrict__ eb,
    float* __restrict__ out_local,
    float* __restrict__ out_global)
{
    __shared__ __align__(16) char sbuf[SZ_YS];   // max(SZ_FS+SZ_WS, SZ_YS)
    __shared__ int ridx[K2_TM];

    float (*fs)[K2_FS] = (float (*)[K2_FS])sbuf;             // [k][sample]
    float (*ws)[K2_WS] = (float (*)[K2_WS])(sbuf + SZ_FS);   // [k][class]
    float (*ys)[K2_YS] = (float (*)[K2_YS])sbuf;             // logits (after GEMM)

    int e   = blockIdx.x;
    int cnt = g_counts[e];
    int m0  = blockIdx.y * K2_TM;
    if (m0 >= cnt) return;

    int tid = threadIdx.x;
    if (tid < K2_TM) {
        int r = m0 + tid;
        ridx[tid] = (r < cnt) ? g_bucket[e * B + r] : -1;
    }
    __syncthreads();

    int ty = tid >> 4;   // sample octet 0..15
    int tx = tid & 15;   // class quad 0..15
    const float* wbase = ew + (size_t)e * C * D;

    unsigned long long acc[4][4];
    #pragma unroll
    for (int p = 0; p < 4; p++)
        #pragma unroll
        for (int j = 0; j < 4; j++)
            acc[p][j] = 0ull;

    for (int k0 = 0; k0 < D; k0 += K2_TK) {
        // stage gathered features: 128 samples x 32 k = 1024 float4, 4/thread
        #pragma unroll
        for (int it = 0; it < 4; it++) {
            int task = tid + it * 256;
            int s  = task >> 3;
            int kc = task & 7;
            int row = ridx[s];
            float4 v = make_float4(0.f, 0.f, 0.f, 0.f);
            if (row >= 0)
                v = *(const float4*)(features + (size_t)row * D + k0 + kc * 4);
            fs[kc * 4 + 0][s] = v.x;
            fs[kc * 4 + 1][s] = v.y;
            fs[kc * 4 + 2][s] = v.z;
            fs[kc * 4 + 3][s] = v.w;
        }
        // stage expert weights: 64 classes x 32 k = 512 float4, 2/thread
        #pragma unroll
        for (int it = 0; it < 2; it++) {
            int task = tid + it * 256;
            int c  = task >> 3;
            int kc = task & 7;
            float4 w = *(const float4*)(wbase + (size_t)c * D + k0 + kc * 4);
            ws[kc * 4 + 0][c] = w.x;
            ws[kc * 4 + 1][c] = w.y;
            ws[kc * 4 + 2][c] = w.z;
            ws[kc * 4 + 3][c] = w.w;
        }
        __syncthreads();

        #pragma unroll
        for (int kk = 0; kk < K2_TK; kk++) {
            ulonglong2 fa0 = *(const ulonglong2*)&fs[kk][ty * 8];
            ulonglong2 fa1 = *(const ulonglong2*)&fs[kk][ty * 8 + 4];
            float4 wb = *(const float4*)&ws[kk][tx * 4];
            unsigned long long w0 = pack2_dup(wb.x);
            unsigned long long w1 = pack2_dup(wb.y);
            unsigned long long w2 = pack2_dup(wb.z);
            unsigned long long w3 = pack2_dup(wb.w);
            unsigned long long f[4] = {fa0.x, fa0.y, fa1.x, fa1.y};
            #pragma unroll
            for (int p = 0; p < 4; p++) {
                acc[p][0] = ffma2(f[p], w0, acc[p][0]);
                acc[p][1] = ffma2(f[p], w1, acc[p][1]);
                acc[p][2] = ffma2(f[p], w2, acc[p][2]);
                acc[p][3] = ffma2(f[p], w3, acc[p][3]);
            }
        }
        __syncthreads();
    }

    // ys aliases fs/ws — everyone is done reading the staging tiles here.
    float4 bias4 = *(const float4*)(eb + e * C + tx * 4);
    float bv[4] = {bias4.x, bias4.y, bias4.z, bias4.w};
    #pragma unroll
    for (int p = 0; p < 4; p++) {
        #pragma unroll
        for (int j = 0; j < 4; j++) {
            float2 v = unpack2(acc[p][j]);
            ys[ty * 8 + 2 * p + 0][tx * 4 + j] = v.x + bv[j];
            ys[ty * 8 + 2 * p + 1][tx * 4 + j] = v.y + bv[j];
        }
    }
    __syncthreads();

    if (tid < K2_TM) {
        int r = m0 + tid;
        if (r < cnt) {
            int row = ridx[tid];
            float m = ys[tid][0];
            int am = 0;
            #pragma unroll
            for (int c = 1; c < C; c++) {
                float v = ys[tid][c];
                if (v > m) { m = v; am = c; }
            }
            float sum = 0.f;
            #pragma unroll
            for (int c = 0; c < C; c++) {
                float v = expf(ys[tid][c] - m);
                ys[tid][c] = v;
                sum += v;
            }
            float inv = 1.0f / sum;
            float* dst = out_local + (size_t)row * C;
            #pragma unroll
            for (int c4 = 0; c4 < C / 4; c4++) {
                float4 v = *(const float4*)&ys[tid][c4 * 4];
                v.x *= inv; v.y *= inv; v.z *= inv; v.w *= inv;
                *(float4*)(dst + c4 * 4) = v;
            }
            out_global[row] = (float)(am + e * C);
        }
    }
}

// ---------------------------------------------------------------------------
// Output layout (reference tuple order, flattened+concatenated, fp32):
//   [0,              B*E)              coarse_output
//   [B*E,            B*E+B)            expert_id (as float)
//   [B*E+B,          B*E+B+B*C)        local_preds
//   [B*E+B+B*C,      B*E+2B+B*C)       global_preds
// ---------------------------------------------------------------------------
extern "C" void kernel_launch(void* const* d_in, const int* in_sizes, int n_in,
                              void* d_out, int out_size) {
    const float* features = (const float*)d_in[0];
    const float* cw       = (const float*)d_in[1];
    const float* cb       = (const float*)d_in[2];
    const float* ew       = (const float*)d_in[3];
    const float* eb       = (const float*)d_in[4];

    float* out        = (float*)d_out;
    float* out_coarse = out;
    float* out_eid    = out + (size_t)B * E;
    float* out_local  = out_eid + B;
    float* out_global = out_local + (size_t)B * C;

    zero_counts_kernel<<<1, 32>>>();
    coarse_kernel<<<B / C1_TM, 256>>>(features, cw, cb, out_coarse, out_eid);
    dim3 g2(E, (B + K2_TM - 1) / K2_TM);
    expert_kernel<<<g2, 256>>>(features, ew, eb, out_local, out_global);
}